// round 10
// baseline (speedup 1.0000x reference)
#include <cuda_runtime.h>
#include <cuda_fp16.h>
#include <cstdint>

// ---------------------------------------------------------------------------
// CFConvAngular: all-MMA, software-pipelined. 256 threads, 2 CTAs/SM.
// Phase A: GEMM1 (H1^T = ssp(Wf1^T @ R^T + bf1))
// Phase B: GEMM2 (D^T = Wf2^T @ H1^T) + epilogue reading z_cur (fp16),
//          interleaved chunk-wise with: r-stage(tile+1) and z-build(tile+1)
//          into z_next (loads issued at chunk top, consumed at chunk bottom).
// out = ssp(acc @ Wout + bout)
// ---------------------------------------------------------------------------

#define B_DIM 2
#define A_DIM 512
#define T_DIM 512
#define F_DIM 128
#define R_DIM 25
#define TT    128
#define NTILES (T_DIM / TT)     // 4
#define NT    256               // 8 warps

__device__ float g_y[B_DIM * A_DIM * F_DIM];

__device__ __forceinline__ uint32_t smem_u32(const void* p) {
    uint32_t a;
    asm("{ .reg .u64 t; cvta.to.shared.u64 t, %1; cvt.u32.u64 %0, t; }" : "=r"(a) : "l"(p));
    return a;
}

__device__ __forceinline__ float sspf(float v) {
    float e = __expf(-fabsf(v));
    return fmaxf(v, 0.0f) + __logf(1.0f + e) - 0.69314718055994530942f;
}

__device__ __forceinline__ void mma16816(float& c0, float& c1, float& c2, float& c3,
                                         uint32_t a0, uint32_t a1, uint32_t a2, uint32_t a3,
                                         uint32_t b0, uint32_t b1) {
    asm volatile("mma.sync.aligned.m16n8k16.row.col.f32.f16.f16.f32 "
                 "{%0,%1,%2,%3}, {%4,%5,%6,%7}, {%8,%9}, {%0,%1,%2,%3};"
                 : "+f"(c0), "+f"(c1), "+f"(c2), "+f"(c3)
                 : "r"(a0), "r"(a1), "r"(a2), "r"(a3), "r"(b0), "r"(b1));
}

__device__ __forceinline__ void ldsm_x4(uint32_t& r0, uint32_t& r1,
                                        uint32_t& r2, uint32_t& r3, uint32_t addr) {
    asm volatile("ldmatrix.sync.aligned.m8n8.x4.shared.b16 {%0,%1,%2,%3}, [%4];"
                 : "=r"(r0), "=r"(r1), "=r"(r2), "=r"(r3) : "r"(addr));
}
__device__ __forceinline__ void ldsm_x4_t(uint32_t& r0, uint32_t& r1,
                                          uint32_t& r2, uint32_t& r3, uint32_t addr) {
    asm volatile("ldmatrix.sync.aligned.m8n8.x4.trans.shared.b16 {%0,%1,%2,%3}, [%4];"
                 : "=r"(r0), "=r"(r1), "=r"(r2), "=r"(r3) : "r"(addr));
}

__device__ __forceinline__ uint32_t h2u(float a, float b) {
    __half2 h = __floats2half2_rn(a, b);
    return *(uint32_t*)&h;
}

// ------------------------- kernel 1: y = x @ Win ---------------------------
__global__ void __launch_bounds__(F_DIM) in2f_kernel(
    const float* __restrict__ x, const float* __restrict__ Win)
{
    __shared__ float sx[F_DIM];
    const int tid = threadIdx.x;
    const int blk = blockIdx.x;
    sx[tid] = x[blk * F_DIM + tid];
    __syncthreads();
    float s0 = 0.f, s1 = 0.f, s2 = 0.f, s3 = 0.f;
#pragma unroll
    for (int i = 0; i < F_DIM; i += 4) {
        s0 = fmaf(sx[i + 0], Win[(i + 0) * F_DIM + tid], s0);
        s1 = fmaf(sx[i + 1], Win[(i + 1) * F_DIM + tid], s1);
        s2 = fmaf(sx[i + 2], Win[(i + 2) * F_DIM + tid], s2);
        s3 = fmaf(sx[i + 3], Win[(i + 3) * F_DIM + tid], s3);
    }
    g_y[blk * F_DIM + tid] = (s0 + s1) + (s2 + s3);
}

// ------------------------- main fused kernel -------------------------------
#define H1T_STRIDE_B 272                 // 128 k-rows x (128 t + pad) fp16
#define RH_STRIDE_B  80                  // 128 t-rows x (32 r + pad) fp16
#define Z_ROW_H 132                      // halves per z row
#define Z_ROW_B 264                      // bytes per z row
#define OFF_H1T  0                       // 34816
#define OFF_RH   34816                   // 10240 -> 45056
#define OFF_Z0   45056                   // 128*264 = 33792 -> 78848
#define OFF_Z1   78848                   // 33792 -> 112640
#define OFF_ACC  112640                  // 512
#define SMEM_BYTES 113152                // x2 = 226304 <= 227KB

__global__ void __launch_bounds__(NT, 2) cfconv_kernel(
    const float* __restrict__ r_ij, const float* __restrict__ mask,
    const float* __restrict__ Wf1, const float* __restrict__ bf1,
    const float* __restrict__ Wf2, const float* __restrict__ bf2,
    const float* __restrict__ Wout, const float* __restrict__ bout,
    const int* __restrict__ nj, const int* __restrict__ nk,
    float* __restrict__ out)
{
    extern __shared__ char smem[];
    const int tid  = threadIdx.x;
    const int lane = tid & 31;
    const int wid  = tid >> 5;
    const int g    = lane >> 2;
    const int tig  = lane & 3;
    const int blk  = blockIdx.x;
    const int b    = blk >> 9;

    float* sAcc = (float*)(smem + OFF_ACC);
    const uint32_t sH1Tu = smem_u32(smem + OFF_H1T);
    const uint32_t sRHu  = smem_u32(smem + OFF_RH);
    __half* sRh = (__half*)(smem + OFF_RH);

    const int rw   = wid * 16;
    const int m_lo = rw + g;
    const int m_hi = rw + g + 8;

    // ---- GEMM1 A-frags: Wf1^T[kc][r], K=32 (r>=25 zero) ----
    uint32_t aW[2][4];
#pragma unroll
    for (int s = 0; s < 2; s++) {
        const int r0 = s * 16 + 2 * tig;
#pragma unroll
        for (int q = 0; q < 4; q++) {
            const int rr = r0 + (q >> 1) * 8;
            const int cc = (q & 1) ? m_hi : m_lo;
            const float v0 = (rr     < R_DIM) ? Wf1[rr * F_DIM + cc]       : 0.f;
            const float v1 = (rr + 1 < R_DIM) ? Wf1[(rr + 1) * F_DIM + cc] : 0.f;
            aW[s][q] = h2u(v0, v1);
        }
    }

    // ---- GEMM2 A-frags: Wf2^T[f][k] ----
    uint32_t aA[8][4];
#pragma unroll
    for (int ks = 0; ks < 8; ks++) {
        const int k0 = ks * 16 + tig * 2;
        aA[ks][0] = h2u(Wf2[k0 * F_DIM + m_lo],       Wf2[(k0 + 1) * F_DIM + m_lo]);
        aA[ks][1] = h2u(Wf2[k0 * F_DIM + m_hi],       Wf2[(k0 + 1) * F_DIM + m_hi]);
        aA[ks][2] = h2u(Wf2[(k0 + 8) * F_DIM + m_lo], Wf2[(k0 + 9) * F_DIM + m_lo]);
        aA[ks][3] = h2u(Wf2[(k0 + 8) * F_DIM + m_hi], Wf2[(k0 + 9) * F_DIM + m_hi]);
    }
    const float bf1_lo = bf1[m_lo], bf1_hi = bf1[m_hi];
    const float bf2_lo = bf2[m_lo], bf2_hi = bf2[m_hi];

    const uint32_t rh_off  = (uint32_t)((lane & 7) * RH_STRIDE_B + (lane >> 3) * 16);
    const uint32_t h1t_off = (uint32_t)(((lane >> 3) * 8 + (lane & 7)) * H1T_STRIDE_B);

    const long   rbase = (long)blk * T_DIM * R_DIM;
    const int    tbase = blk * T_DIM;
    const float* ybase = g_y + (long)b * A_DIM * F_DIM;
    const int    zb_f4 = lane * 4;

    float acc_lo = 0.f, acc_hi = 0.f;

    // ---- prologue: stage r(0) ----
    {
        const float* rsrc = r_ij + rbase;
#pragma unroll
        for (int e = tid; e < TT * 32; e += NT) {
            const int t = e >> 5, r = e & 31;
            const float v = (r < R_DIM) ? rsrc[t * R_DIM + r] : 0.f;
            sRh[t * (RH_STRIDE_B / 2) + r] = __float2half_rn(v);
        }
    }
    // ---- prologue: z(0) into Z0 (2 threads per t-row, one chase depth) ----
    {
        const int t  = tid >> 1;
        const int fh = (tid & 1) * 16;            // float4-index base (64 f)
        const int jj = nj[tbase + t], kk = nk[tbase + t];
        const float m = mask[tbase + t];
        const float4* yj = (const float4*)(ybase + jj * F_DIM) + fh;
        const float4* yk = (const float4*)(ybase + kk * F_DIM) + fh;
        uint2* zdst = (uint2*)(smem + OFF_Z0 + t * Z_ROW_B + fh * 8);
#pragma unroll
        for (int q = 0; q < 16; q++) {
            const float4 a = yj[q], bb = yk[q];
            uint2 p;
            p.x = h2u(a.x * bb.x * m, a.y * bb.y * m);
            p.y = h2u(a.z * bb.z * m, a.w * bb.w * m);
            zdst[q] = p;
        }
    }
    __syncthreads();

    for (int tile = 0; tile < NTILES; ++tile) {
        const __half* zc = (const __half*)(smem + ((tile & 1) ? OFF_Z1 : OFF_Z0));
        char*         zn = smem + ((tile & 1) ? OFF_Z0 : OFF_Z1);

        // ================= Phase A: GEMM1 =================
#pragma unroll 4
        for (int nb = 0; nb < 16; nb++) {
            uint32_t q0, q1, q2, q3;
            ldsm_x4(q0, q1, q2, q3, sRHu + (uint32_t)(nb * 8 * RH_STRIDE_B) + rh_off);
            float c0 = 0.f, c1 = 0.f, c2 = 0.f, c3 = 0.f;
            mma16816(c0, c1, c2, c3, aW[0][0], aW[0][1], aW[0][2], aW[0][3], q0, q1);
            mma16816(c0, c1, c2, c3, aW[1][0], aW[1][1], aW[1][2], aW[1][3], q2, q3);
            const int t0 = nb * 8 + 2 * tig;
            const uint32_t u_lo = h2u(sspf(c0 + bf1_lo), sspf(c1 + bf1_lo));
            const uint32_t u_hi = h2u(sspf(c2 + bf1_hi), sspf(c3 + bf1_hi));
            *(uint32_t*)(smem + OFF_H1T + m_lo * H1T_STRIDE_B + t0 * 2) = u_lo;
            *(uint32_t*)(smem + OFF_H1T + m_hi * H1T_STRIDE_B + t0 * 2) = u_hi;
        }
        __syncthreads();

        // ===== Phase B: G2 + epilogue, interleaved stage(n+1)/z(n+1) =====
        const bool  more  = (tile + 1 < NTILES);
        const int   toffn = tbase + (tile + 1) * TT;
        const float* rsrcn = r_ij + rbase + (long)(tile + 1) * TT * R_DIM;

        // per-tile index prefetch: lanes 0..15 hold (j,k,m) for rows i*8+wid
        int jreg = 0, kreg = 0; float mreg = 0.f;
        if (more && lane < 16) {
            const int t = lane * 8 + wid;
            jreg = nj[toffn + t];
            kreg = nk[toffn + t];
            mreg = mask[toffn + t];
        }

#pragma unroll 2
        for (int c = 0; c < 8; c++) {
            // --- chunk top: issue long-latency loads ---
            float rv0 = 0.f, rv1 = 0.f;
            const int re0 = tid + (2 * c) * NT;
            const int re1 = re0 + NT;
            if (more) {
                rv0 = ((re0 & 31) < R_DIM) ? rsrcn[(re0 >> 5) * R_DIM + (re0 & 31)] : 0.f;
                rv1 = ((re1 & 31) < R_DIM) ? rsrcn[(re1 >> 5) * R_DIM + (re1 & 31)] : 0.f;
            }
            const int jj0 = __shfl_sync(0xFFFFFFFFu, jreg, 2 * c);
            const int kk0 = __shfl_sync(0xFFFFFFFFu, kreg, 2 * c);
            const float m0 = __shfl_sync(0xFFFFFFFFu, mreg, 2 * c);
            const int jj1 = __shfl_sync(0xFFFFFFFFu, jreg, 2 * c + 1);
            const int kk1 = __shfl_sync(0xFFFFFFFFu, kreg, 2 * c + 1);
            const float m1 = __shfl_sync(0xFFFFFFFFu, mreg, 2 * c + 1);
            float4 yj0, yk0, yj1, yk1;
            if (more) {
                yj0 = *(const float4*)(ybase + jj0 * F_DIM + zb_f4);
                yk0 = *(const float4*)(ybase + kk0 * F_DIM + zb_f4);
                yj1 = *(const float4*)(ybase + jj1 * F_DIM + zb_f4);
                yk1 = *(const float4*)(ybase + kk1 * F_DIM + zb_f4);
            }

            // --- middle: 2 GEMM2 nb-blocks + epilogue (covers the latency) ---
#pragma unroll
            for (int u = 0; u < 2; u++) {
                const int nb = 2 * c + u;
                float c0 = 0.f, c1 = 0.f, c2 = 0.f, c3 = 0.f;
#pragma unroll
                for (int kq = 0; kq < 4; kq++) {
                    uint32_t q0, q1, q2, q3;
                    ldsm_x4_t(q0, q1, q2, q3,
                              sH1Tu + (uint32_t)(kq * 32 * H1T_STRIDE_B) + h1t_off
                                    + (uint32_t)(nb * 16));
                    mma16816(c0, c1, c2, c3,
                             aA[2 * kq][0], aA[2 * kq][1], aA[2 * kq][2], aA[2 * kq][3],
                             q0, q1);
                    mma16816(c0, c1, c2, c3,
                             aA[2 * kq + 1][0], aA[2 * kq + 1][1], aA[2 * kq + 1][2], aA[2 * kq + 1][3],
                             q2, q3);
                }
                const int t_a = nb * 8 + tig * 2;
                const int t_b = t_a + 1;
                const float za_lo = __half2float(zc[t_a * Z_ROW_H + m_lo]);
                const float zb_lo = __half2float(zc[t_b * Z_ROW_H + m_lo]);
                const float za_hi = __half2float(zc[t_a * Z_ROW_H + m_hi]);
                const float zb_hi = __half2float(zc[t_b * Z_ROW_H + m_hi]);
                acc_lo = fmaf(c0 + bf2_lo, za_lo, acc_lo);
                acc_lo = fmaf(c1 + bf2_lo, zb_lo, acc_lo);
                acc_hi = fmaf(c2 + bf2_hi, za_hi, acc_hi);
                acc_hi = fmaf(c3 + bf2_hi, zb_hi, acc_hi);
            }

            // --- chunk bottom: consume loads, store r(n+1) and z(n+1) ---
            if (more) {
                sRh[(re0 >> 5) * (RH_STRIDE_B / 2) + (re0 & 31)] = __float2half_rn(rv0);
                sRh[(re1 >> 5) * (RH_STRIDE_B / 2) + (re1 & 31)] = __float2half_rn(rv1);
                const int tz0 = 16 * c + wid;
                const int tz1 = tz0 + 8;
                uint2 p0, p1;
                p0.x = h2u(yj0.x * yk0.x * m0, yj0.y * yk0.y * m0);
                p0.y = h2u(yj0.z * yk0.z * m0, yj0.w * yk0.w * m0);
                p1.x = h2u(yj1.x * yk1.x * m1, yj1.y * yk1.y * m1);
                p1.y = h2u(yj1.z * yk1.z * m1, yj1.w * yk1.w * m1);
                *(uint2*)(zn + tz0 * Z_ROW_B + lane * 8) = p0;
                *(uint2*)(zn + tz1 * Z_ROW_B + lane * 8) = p1;
            }
        }
        __syncthreads();
    }

    // ---- quad reduction and publish ----
    acc_lo += __shfl_xor_sync(0xFFFFFFFF, acc_lo, 1);
    acc_lo += __shfl_xor_sync(0xFFFFFFFF, acc_lo, 2);
    acc_hi += __shfl_xor_sync(0xFFFFFFFF, acc_hi, 1);
    acc_hi += __shfl_xor_sync(0xFFFFFFFF, acc_hi, 2);
    if (tig == 0) {
        sAcc[m_lo] = acc_lo;
        sAcc[m_hi] = acc_hi;
    }
    __syncthreads();

    // ---- f2out ----
    if (tid < F_DIM) {
        float s0 = 0.f, s1 = 0.f, s2 = 0.f, s3 = 0.f;
#pragma unroll
        for (int f = 0; f < F_DIM; f += 4) {
            s0 = fmaf(sAcc[f + 0], Wout[(f + 0) * F_DIM + tid], s0);
            s1 = fmaf(sAcc[f + 1], Wout[(f + 1) * F_DIM + tid], s1);
            s2 = fmaf(sAcc[f + 2], Wout[(f + 2) * F_DIM + tid], s2);
            s3 = fmaf(sAcc[f + 3], Wout[(f + 3) * F_DIM + tid], s3);
        }
        out[blk * F_DIM + tid] = sspf((s0 + s1) + (s2 + s3) + bout[tid]);
    }
}

// ------------------------------- launcher ----------------------------------
extern "C" void kernel_launch(void* const* d_in, const int* in_sizes, int n_in,
                              void* d_out, int out_size)
{
    const float* x    = (const float*)d_in[0];
    const float* r_ij = (const float*)d_in[1];
    const float* mask = (const float*)d_in[2];
    const float* Wf1  = (const float*)d_in[3];
    const float* bf1  = (const float*)d_in[4];
    const float* Wf2  = (const float*)d_in[5];
    const float* bf2  = (const float*)d_in[6];
    const float* Win  = (const float*)d_in[7];
    const float* Wout = (const float*)d_in[8];
    const float* bout = (const float*)d_in[9];
    const int*   nj   = (const int*)d_in[10];
    const int*   nk   = (const int*)d_in[11];
    float* out = (float*)d_out;

    cudaFuncSetAttribute(cfconv_kernel,
                         cudaFuncAttributeMaxDynamicSharedMemorySize, SMEM_BYTES);

    in2f_kernel<<<B_DIM * A_DIM, F_DIM>>>(x, Win);
    cfconv_kernel<<<B_DIM * A_DIM, NT, SMEM_BYTES>>>(
        r_ij, mask, Wf1, bf1, Wf2, bf2, Wout, bout, nj, nk, out);
}